// round 1
// baseline (speedup 1.0000x reference)
#include <cuda_runtime.h>
#include <math.h>

#define TOKENS 1024
#define CDIM   512
#define QKVD   1536
#define NSEQ   256
#define HEADS  8
#define DH     64
#define QT     32
#define KT     64
#define EPSF   1e-6f

// scratch (allocation-free rule: device globals)
__device__ float g_qkv[TOKENS * QKVD];   // (B*N, 3C) qkv projection
__device__ float g_att[TOKENS * CDIM];   // attention output before proj

// ---------------------------------------------------------------------------
// SGEMM: C[M, Ncols] = A[M, K] * Bw[Ncols, K]^T (+ bias), M/Ncols mult of 64,
// K mult of 16. 64x64 block tile, 4x4 per thread, 256 threads.
// ---------------------------------------------------------------------------
__global__ __launch_bounds__(256)
void sgemm_nt(const float* __restrict__ A, const float* __restrict__ Bw,
              const float* __restrict__ bias, float* __restrict__ C,
              int Ncols, int K)
{
    __shared__ __align__(16) float As[16][64];
    __shared__ __align__(16) float Bs[16][64];
    const int tid = threadIdx.x;
    const int m0 = blockIdx.y * 64;
    const int n0 = blockIdx.x * 64;
    const int tx = tid & 15, ty = tid >> 4;
    const int fr = tid >> 2;          // 0..63 tile row
    const int fc = (tid & 3) << 2;    // 0,4,8,12 within BK=16

    float acc[4][4];
    #pragma unroll
    for (int i = 0; i < 4; i++)
        #pragma unroll
        for (int j = 0; j < 4; j++) acc[i][j] = 0.f;

    for (int k0 = 0; k0 < K; k0 += 16) {
        float4 av = *(const float4*)&A [(m0 + fr) * K + k0 + fc];
        float4 bv = *(const float4*)&Bw[(n0 + fr) * K + k0 + fc];
        As[fc+0][fr] = av.x; As[fc+1][fr] = av.y; As[fc+2][fr] = av.z; As[fc+3][fr] = av.w;
        Bs[fc+0][fr] = bv.x; Bs[fc+1][fr] = bv.y; Bs[fc+2][fr] = bv.z; Bs[fc+3][fr] = bv.w;
        __syncthreads();
        #pragma unroll
        for (int k = 0; k < 16; k++) {
            float4 a4 = *(const float4*)&As[k][ty << 2];
            float4 b4 = *(const float4*)&Bs[k][tx << 2];
            float ar[4] = {a4.x, a4.y, a4.z, a4.w};
            float br[4] = {b4.x, b4.y, b4.z, b4.w};
            #pragma unroll
            for (int i = 0; i < 4; i++)
                #pragma unroll
                for (int j = 0; j < 4; j++)
                    acc[i][j] = fmaf(ar[i], br[j], acc[i][j]);
        }
        __syncthreads();
    }
    float4 bb = make_float4(0.f, 0.f, 0.f, 0.f);
    if (bias) bb = *(const float4*)&bias[n0 + (tx << 2)];
    #pragma unroll
    for (int i = 0; i < 4; i++) {
        float4 o;
        o.x = acc[i][0] + bb.x; o.y = acc[i][1] + bb.y;
        o.z = acc[i][2] + bb.z; o.w = acc[i][3] + bb.w;
        *(float4*)&C[(m0 + (ty << 2) + i) * Ncols + n0 + (tx << 2)] = o;
    }
}

// ---------------------------------------------------------------------------
// Fourier attention core. One block = (b, h, 32-query tile).
// score(i,j) = prod_d sin(R(q-k))/(q-k); use sin(Rq)cos(Rk)-cos(Rq)sin(Rk)
// and accumulate numerator/denominator products separately (1 div per pair).
// |q-k| < 0.01 -> 2-term Taylor of sin(Rd)/d into numerator (den factor = 1),
// which also covers the reference's |d|<1e-8 -> R branch exactly.
// Then a4 = score^4, row-normalize by (sum + eps), multiply by V.
// ---------------------------------------------------------------------------
__global__ __launch_bounds__(256, 2)
void fourier_attn(const float* __restrict__ qkv, const float* __restrict__ paramR,
                  float* __restrict__ attout)
{
    extern __shared__ float sm[];
    float* sQq = sm;                   // [DH][QT]
    float* sQs = sQq + DH * QT;
    float* sQc = sQs + DH * QT;
    float* sKk = sQc + DH * QT;        // [KT][DH]
    float* sKs = sKk + KT * DH;
    float* sKc = sKs + KT * DH;
    float* sS  = sKc + KT * DH;        // [NSEQ][QT]  (a4)
    float* sRed = sS + NSEQ * QT;      // [8][QT]
    float* sInv = sRed + 8 * QT;       // [QT]
    float* sV  = sKk;                  // reuse K region for V in PV phase

    const int tid = threadIdx.x;
    const int q   = tid & 31;          // query within tile
    const int kg  = tid >> 5;          // key-group (8 keys) / dim-slice in PV
    const int qt  = blockIdx.x;
    const int h   = blockIdx.y;
    const int b   = blockIdx.z;
    const int tok0 = b * NSEQ;
    const int q0  = qt * QT;

    const float R  = paramR[0];
    const float c3 = -R * R * R * (1.f / 6.f);

    // ---- Q side: values + sin/cos, layout [d][q] for conflict-free reads ----
    for (int i = tid; i < QT * DH; i += 256) {
        int qq = i & 31, d = i >> 5;
        float v = qkv[(tok0 + q0 + qq) * QKVD + h * DH + d];
        float s, c; sincosf(R * v, &s, &c);
        sQq[d * QT + qq] = v; sQs[d * QT + qq] = s; sQc[d * QT + qq] = c;
    }

    const int kcol = CDIM + h * DH;
    for (int kc0 = 0; kc0 < NSEQ; kc0 += KT) {
        __syncthreads();
        for (int i = tid; i < KT * DH; i += 256) {
            int kk = i >> 6, d = i & 63;
            float v = qkv[(tok0 + kc0 + kk) * QKVD + kcol + d];
            float s, c; sincosf(R * v, &s, &c);
            sKk[i] = v; sKs[i] = s; sKc[i] = c;
        }
        __syncthreads();

        float np[8], dp[8];
        #pragma unroll
        for (int j = 0; j < 8; j++) { np[j] = 1.f; dp[j] = 1.f; }
        const float* kkp = sKk + kg * 8 * DH;
        const float* ksp = sKs + kg * 8 * DH;
        const float* kcp = sKc + kg * 8 * DH;
        #pragma unroll 2
        for (int d = 0; d < DH; d++) {
            float qv = sQq[d * QT + q];
            float qs = sQs[d * QT + q];
            float qc = sQc[d * QT + q];
            #pragma unroll
            for (int j = 0; j < 8; j++) {
                float kv  = kkp[j * DH + d];
                float ks  = ksp[j * DH + d];
                float kco = kcp[j * DH + d];
                float diff = qv - kv;
                float num  = fmaf(qs, kco, -(qc * ks));   // sin(R(q-k))
                float vs   = fmaf(diff * diff, c3, R);    // Taylor sin(Rd)/d
                bool small = fabsf(diff) < 0.01f;
                np[j] *= small ? vs : num;
                dp[j] *= small ? 1.f : diff;
            }
        }
        #pragma unroll
        for (int j = 0; j < 8; j++) {
            float s  = (dp[j] != 0.f) ? np[j] / dp[j] : 0.f;
            float s2 = s * s;
            sS[(kc0 + kg * 8 + j) * QT + q] = s2 * s2;    // score^4
        }
    }
    __syncthreads();

    // ---- row sums of a4 ----
    {
        float part = 0.f;
        #pragma unroll 8
        for (int j = kg * 32; j < kg * 32 + 32; j++) part += sS[j * QT + q];
        sRed[kg * QT + q] = part;
    }
    __syncthreads();
    if (kg == 0) {
        float ssum = 0.f;
        #pragma unroll
        for (int r = 0; r < 8; r++) ssum += sRed[r * QT + q];
        sInv[q] = 1.f / (ssum + EPSF);
    }

    // ---- PV: out[q][d] = (sum_j a4[q][j] * v[j][d]) * rinv[q] ----
    float acc[8];
    #pragma unroll
    for (int i = 0; i < 8; i++) acc[i] = 0.f;
    const int vcol = 2 * CDIM + h * DH;
    for (int kc0 = 0; kc0 < NSEQ; kc0 += KT) {
        __syncthreads();
        for (int i = tid; i < KT * DH; i += 256)
            sV[i] = qkv[(tok0 + kc0 + (i >> 6)) * QKVD + vcol + (i & 63)];
        __syncthreads();
        for (int jj = 0; jj < KT; jj++) {
            float a = sS[(kc0 + jj) * QT + q];
            float4 v0 = *(const float4*)&sV[jj * DH + kg * 8];
            float4 v1 = *(const float4*)&sV[jj * DH + kg * 8 + 4];
            acc[0] = fmaf(a, v0.x, acc[0]);
            acc[1] = fmaf(a, v0.y, acc[1]);
            acc[2] = fmaf(a, v0.z, acc[2]);
            acc[3] = fmaf(a, v0.w, acc[3]);
            acc[4] = fmaf(a, v1.x, acc[4]);
            acc[5] = fmaf(a, v1.y, acc[5]);
            acc[6] = fmaf(a, v1.z, acc[6]);
            acc[7] = fmaf(a, v1.w, acc[7]);
        }
    }
    float rinv = sInv[q];
    float4 o0, o1;
    o0.x = acc[0] * rinv; o0.y = acc[1] * rinv; o0.z = acc[2] * rinv; o0.w = acc[3] * rinv;
    o1.x = acc[4] * rinv; o1.y = acc[5] * rinv; o1.z = acc[6] * rinv; o1.w = acc[7] * rinv;
    float* dst = &attout[(tok0 + q0 + q) * CDIM + h * DH + kg * 8];
    *(float4*)dst       = o0;
    *(float4*)(dst + 4) = o1;
}

static const int ATTN_SMEM = (3 * DH * QT + 3 * KT * DH + NSEQ * QT + 8 * QT + QT) * 4;

extern "C" void kernel_launch(void* const* d_in, const int* in_sizes, int n_in,
                              void* d_out, int out_size)
{
    const float* x      = (const float*)d_in[0];
    const float* w_qkv  = (const float*)d_in[1];
    const float* w_proj = (const float*)d_in[2];
    const float* b_proj = (const float*)d_in[3];
    const float* paramR = (const float*)d_in[4];
    float* out = (float*)d_out;

    float *qkvbuf, *attbuf;
    cudaGetSymbolAddress((void**)&qkvbuf, g_qkv);
    cudaGetSymbolAddress((void**)&attbuf, g_att);

    cudaFuncSetAttribute(fourier_attn, cudaFuncAttributeMaxDynamicSharedMemorySize,
                         ATTN_SMEM);

    // 1) qkv = x @ w_qkv^T   (1024 x 1536, K=512)
    sgemm_nt<<<dim3(QKVD / 64, TOKENS / 64), 256>>>(x, w_qkv, nullptr, qkvbuf,
                                                    QKVD, CDIM);
    // 2) Fourier attention core -> g_att (1024 x 512)
    fourier_attn<<<dim3(NSEQ / QT, HEADS, 4), 256, ATTN_SMEM>>>(qkvbuf, paramR,
                                                                attbuf);
    // 3) out = g_att @ w_proj^T + b_proj
    sgemm_nt<<<dim3(CDIM / 64, TOKENS / 64), 256>>>(attbuf, w_proj, b_proj, out,
                                                    CDIM, CDIM);
}